// round 11
// baseline (speedup 1.0000x reference)
#include <cuda_runtime.h>
#include <cuda_bf16.h>
#include <cstdint>

// Problem constants
#define BATCH 2
#define SEQ   2048
#define HID   1024
#define HEADS 16
#define HDIM  64
#define QKVW  (3*HID)      // 3072
#define MROWS (BATCH*SEQ)  // 4096
#define KDIM  1024
#define NHB   (BATCH*HEADS)   // 32
#define KPAD  2304            // 2048 + 2*128 pad

// Scratch (device globals — no allocation allowed)
__device__ float g_qkv[(size_t)MROWS * QKVW];   // [B,S,3,H,D] (pre-rope)
__device__ float g_att[(size_t)MROWS * HID];    // [B,S,H,D] (tf32-rounded)
__device__ float g_hsr[(size_t)MROWS * KDIM];   // hs, tf32-rounded
__device__ float g_wqT[(size_t)QKVW * KDIM];    // Wqkv^T [N][K]
__device__ float g_woT[(size_t)HID * KDIM];     // Wo^T   [N][K]
// attention operands (tf32 hi/lo, per-head K-major)
__device__ float g_qh[(size_t)NHB * SEQ * HDIM];
__device__ float g_ql[(size_t)NHB * SEQ * HDIM];
__device__ float g_kh[(size_t)NHB * KPAD * HDIM];
__device__ float g_kl[(size_t)NHB * KPAD * HDIM];
__device__ float g_vth[(size_t)NHB * HDIM * KPAD];
__device__ float g_vtl[(size_t)NHB * HDIM * KPAD];

// ---------------------------------------------------------------------------
// PTX helpers
// ---------------------------------------------------------------------------
__device__ __forceinline__ float tf32r(float x) {
    uint32_t u;
    asm("cvt.rna.tf32.f32 %0, %1;" : "=r"(u) : "f"(x));
    return __uint_as_float(u);
}
__device__ __forceinline__ uint32_t s2u(const void* p) {
    uint32_t a;
    asm("{ .reg .u64 t; cvta.to.shared.u64 t, %1; cvt.u32.u64 %0, t; }"
        : "=r"(a) : "l"(p));
    return a;
}
__device__ __forceinline__ void mma_tf32(float* d, const uint32_t* a, const uint32_t* b) {
    asm volatile(
        "mma.sync.aligned.m16n8k8.row.col.f32.tf32.tf32.f32 "
        "{%0,%1,%2,%3}, {%4,%5,%6,%7}, {%8,%9}, {%0,%1,%2,%3};\n"
        : "+f"(d[0]), "+f"(d[1]), "+f"(d[2]), "+f"(d[3])
        : "r"(a[0]), "r"(a[1]), "r"(a[2]), "r"(a[3]),
          "r"(b[0]), "r"(b[1]));
}
__device__ __forceinline__ void cp_async16(uint32_t saddr, const void* g) {
    asm volatile("cp.async.cg.shared.global [%0], [%1], 16;" :: "r"(saddr), "l"(g));
}
__device__ __forceinline__ void cp_commit() {
    asm volatile("cp.async.commit_group;" ::: "memory");
}
__device__ __forceinline__ void cp_wait1() {
    asm volatile("cp.async.wait_group 1;" ::: "memory");
}
__device__ __forceinline__ void ldsm_x4(uint32_t* r, uint32_t addr) {
    asm volatile("ldmatrix.sync.aligned.m8n8.x4.shared.b16 {%0,%1,%2,%3}, [%4];"
                 : "=r"(r[0]), "=r"(r[1]), "=r"(r[2]), "=r"(r[3]) : "r"(addr));
}

// ---------------------------------------------------------------------------
// Pre-pass kernels
// ---------------------------------------------------------------------------
__global__ void round_tf32(const float* __restrict__ x, float* __restrict__ y, int n)
{
    int i = (blockIdx.x * blockDim.x + threadIdx.x) * 4;
    if (i >= n) return;
    float4 v = *(const float4*)(x + i);
    v.x = tf32r(v.x); v.y = tf32r(v.y); v.z = tf32r(v.z); v.w = tf32r(v.w);
    *(float4*)(y + i) = v;
}

__global__ void transpose_round(const float* __restrict__ W, float* __restrict__ T,
                                int K, int N)
{
    __shared__ float t[32][33];
    int n0 = blockIdx.x * 32, k0 = blockIdx.y * 32;
    int tx = threadIdx.x, ty = threadIdx.y;
#pragma unroll
    for (int i = 0; i < 4; i++)
        t[ty + 8 * i][tx] = W[(size_t)(k0 + ty + 8 * i) * N + n0 + tx];
    __syncthreads();
#pragma unroll
    for (int i = 0; i < 4; i++)
        T[(size_t)(n0 + ty + 8 * i) * K + k0 + tx] = tf32r(t[tx][ty + 8 * i]);
}

// RoPE + tf32 hi/lo split for q,k into per-head K-major layouts.
// q: [hb][s][64]; k: [hb][s+128][64] (padded key index).
__global__ void rope_split(const float* __restrict__ qkv, const float* __restrict__ cache,
                           float* __restrict__ qh, float* __restrict__ ql,
                           float* __restrict__ kh, float* __restrict__ kl)
{
    int idx = blockIdx.x * blockDim.x + threadIdx.x;   // 2^21 total
    int d4   = idx & 15;
    int s    = (idx >> 4) & (SEQ - 1);
    int h    = (idx >> 15) & 15;
    int kind = (idx >> 19) & 1;
    int b    = idx >> 20;

    size_t src = ((size_t)(b * SEQ + s)) * QKVW + kind * HID + h * HDIM + d4 * 4;
    float4 x = *(const float4*)(qkv + src);
    int pos = s & 255;
    int d2 = d4 * 2;
    float2 cs0 = *(const float2*)(cache + (pos * 32 + d2) * 2);
    float2 cs1 = *(const float2*)(cache + (pos * 32 + d2 + 1) * 2);
    float4 y;
    y.x = x.x * cs0.x - x.y * cs0.y;
    y.y = x.y * cs0.x + x.x * cs0.y;
    y.z = x.z * cs1.x - x.w * cs1.y;
    y.w = x.w * cs1.x + x.z * cs1.y;

    float4 hi, lo;
    hi.x = tf32r(y.x); lo.x = tf32r(y.x - hi.x);
    hi.y = tf32r(y.y); lo.y = tf32r(y.y - hi.y);
    hi.z = tf32r(y.z); lo.z = tf32r(y.z - hi.z);
    hi.w = tf32r(y.w); lo.w = tf32r(y.w - hi.w);

    int hb = b * HEADS + h;
    if (kind == 0) {
        size_t o = ((size_t)(hb * SEQ + s)) * HDIM + d4 * 4;
        *(float4*)(qh + o) = hi;
        *(float4*)(ql + o) = lo;
    } else {
        size_t o = ((size_t)hb * KPAD + s + 128) * HDIM + d4 * 4;
        *(float4*)(kh + o) = hi;
        *(float4*)(kl + o) = lo;
    }
}

// V transpose + split: vT [hb][d][s+128] (padded key columns).
__global__ void vt_split(const float* __restrict__ qkv,
                         float* __restrict__ vth, float* __restrict__ vtl)
{
    __shared__ float t[32][33];
    int hb = blockIdx.z;
    int b = hb >> 4, h = hb & 15;
    int s0 = blockIdx.x * 32, d0 = blockIdx.y * 32;
    int tx = threadIdx.x, ty = threadIdx.y;
#pragma unroll
    for (int i = 0; i < 4; i++)
        t[ty + 8 * i][tx] =
            qkv[((size_t)(b * SEQ + s0 + ty + 8 * i)) * QKVW + 2 * HID + h * HDIM + d0 + tx];
    __syncthreads();
#pragma unroll
    for (int i = 0; i < 4; i++) {
        float v = t[tx][ty + 8 * i];
        float hi = tf32r(v);
        size_t o = ((size_t)hb * HDIM + d0 + ty + 8 * i) * KPAD + 128 + s0 + tx;
        vth[o] = hi;
        vtl[o] = tf32r(v - hi);
    }
}

// Zero the pad regions of k and vT (so OOB keys contribute exact zeros).
__global__ void pad_zero(float* __restrict__ kh, float* __restrict__ kl,
                         float* __restrict__ vth, float* __restrict__ vtl)
{
    int idx = blockIdx.x * blockDim.x + threadIdx.x;  // 2^20
    int which = idx >> 19;
    int r = idx & 524287;
    if (which == 0) {
        int hb = r >> 14;
        int row = (r >> 6) & 255;
        int d = r & 63;
        int sidx = row < 128 ? row : row + SEQ;
        size_t o = ((size_t)hb * KPAD + sidx) * HDIM + d;
        kh[o] = 0.0f; kl[o] = 0.0f;
    } else {
        int hb = r >> 14;
        int d = (r >> 8) & 63;
        int c = r & 255;
        int col = c < 128 ? c : c + SEQ;
        size_t o = ((size_t)hb * HDIM + d) * KPAD + col;
        vth[o] = 0.0f; vtl[o] = 0.0f;
    }
}

// ---------------------------------------------------------------------------
// tf32 GEMM, cp.async + ldmatrix + mma (unchanged from round 10)
// ---------------------------------------------------------------------------
#define GSMEM (3 * 32768)

__global__ __launch_bounds__(256) void gemm_tf32_cp(
    const float* __restrict__ A, const float* __restrict__ Bt,
    const float* __restrict__ bias, float* __restrict__ C, int N)
{
    extern __shared__ char smc[];
    const uint32_t sbase = s2u(smc);
    const int tid = threadIdx.x, lane = tid & 31, wid = tid >> 5;
    const int wm = wid >> 1, wn = wid & 1;
    const int m0 = blockIdx.y * 128, n0 = blockIdx.x * 128;

    float acc[2][8][4];
#pragma unroll
    for (int i = 0; i < 2; i++)
#pragma unroll
        for (int j = 0; j < 8; j++)
#pragma unroll
            for (int c = 0; c < 4; c++) acc[i][j][c] = 0.0f;

#define ISSUE(ck, st)                                                         \
    {                                                                         \
        const float* pA_ = A + (size_t)m0 * KDIM + (ck) * 32;                 \
        const float* pB_ = Bt + (size_t)n0 * KDIM + (ck) * 32;                \
        uint32_t sa_ = sbase + (uint32_t)(st) * 32768u;                       \
        _Pragma("unroll")                                                     \
        for (int i_ = 0; i_ < 4; i_++) {                                      \
            int u_ = tid + i_ * 256;                                          \
            int row_ = u_ >> 3, c_ = u_ & 7;                                  \
            uint32_t off_ = row_ * 128 + ((c_ ^ (row_ & 7)) << 4);            \
            cp_async16(sa_ + off_, pA_ + (size_t)row_ * KDIM + c_ * 4);       \
            cp_async16(sa_ + 16384u + off_, pB_ + (size_t)row_ * KDIM + c_ * 4); \
        }                                                                     \
    }

    ISSUE(0, 0); cp_commit();
    ISSUE(1, 1); cp_commit();

    const int g = lane >> 3, l7 = lane & 7;
    int st = 0;
    for (int ck = 0; ck < KDIM / 32; ck++) {
        cp_wait1();
        __syncthreads();
        int nst = st + 2; if (nst >= 3) nst -= 3;
        if (ck + 2 < KDIM / 32) ISSUE(ck + 2, nst);
        cp_commit();

        uint32_t sa = sbase + (uint32_t)st * 32768u;
        uint32_t sb = sa + 16384u;
#pragma unroll
        for (int kt = 0; kt < 4; kt++) {
            uint32_t a[2][4];
#pragma unroll
            for (int mt = 0; mt < 2; mt++) {
                int row = wm * 32 + mt * 16 + ((g & 1) << 3) + l7;
                int c = 2 * kt + (g >> 1);
                ldsm_x4(a[mt], sa + row * 128 + ((c ^ l7) << 4));
            }
            uint32_t b[8][2];
#pragma unroll
            for (int p = 0; p < 4; p++) {
                int row = wn * 64 + p * 16 + ((g >> 1) << 3) + l7;
                int c = 2 * kt + (g & 1);
                uint32_t r4[4];
                ldsm_x4(r4, sb + row * 128 + ((c ^ l7) << 4));
                b[2 * p][0] = r4[0]; b[2 * p][1] = r4[1];
                b[2 * p + 1][0] = r4[2]; b[2 * p + 1][1] = r4[3];
            }
#pragma unroll
            for (int mt = 0; mt < 2; mt++)
#pragma unroll
                for (int nt = 0; nt < 8; nt++)
                    mma_tf32(acc[mt][nt], a[mt], b[nt]);
        }
        st++; if (st == 3) st = 0;
    }
#undef ISSUE

    const int gr = lane >> 2;
    const int gc = (lane & 3) << 1;
#pragma unroll
    for (int nt = 0; nt < 8; nt++) {
        int col = n0 + wn * 64 + nt * 8 + gc;
        float2 bb = *(const float2*)(bias + col);
#pragma unroll
        for (int mt = 0; mt < 2; mt++) {
            int row = m0 + wm * 32 + mt * 16 + gr;
            float2 v0, v1;
            v0.x = acc[mt][nt][0] + bb.x;
            v0.y = acc[mt][nt][1] + bb.y;
            v1.x = acc[mt][nt][2] + bb.x;
            v1.y = acc[mt][nt][3] + bb.y;
            *(float2*)(C + (size_t)row * N + col)       = v0;
            *(float2*)(C + (size_t)(row + 8) * N + col) = v1;
        }
    }
}

// ---------------------------------------------------------------------------
// Banded attention: cp.async + ldmatrix + 3xTF32 mma everywhere.
// Block = (q-tile 64, hb), 256 threads (8 warps: 4m x 2n of 16x32).
// SMEM: Q hi/lo 32KB | KV ring 2 x (hi 16KB + lo 16KB) | sc 64x321 | red.
// Tiles u=0..9 (K0..K4,V0..V4) flow through the 2-stage ring; tile u lives in
// stage u&1; tile u+2 is issued right after tile u's compute.
// ---------------------------------------------------------------------------
#define SC_OFF   98304
#define RED_OFF  180480
#define ATT_SMEM 181504

__device__ __forceinline__ void stage_k(uint32_t dst, const float* __restrict__ kh,
                                        const float* __restrict__ kl,
                                        int hb, int s0, int tid)
{
    const float* ph = kh + ((size_t)hb * KPAD + s0) * HDIM;
    const float* pl = kl + ((size_t)hb * KPAD + s0) * HDIM;
#pragma unroll
    for (int i = 0; i < 4; i++) {
        int u = tid + i * 256;
        int row = u >> 4, c = u & 15;
        uint32_t swc = (c & 8) | ((c ^ (row & 7)) & 7);
        uint32_t off = row * 256 + (swc << 4);
        cp_async16(dst + off, ph + (size_t)row * HDIM + c * 4);
        cp_async16(dst + 16384u + off, pl + (size_t)row * HDIM + c * 4);
    }
}
__device__ __forceinline__ void stage_v(uint32_t dst, const float* __restrict__ vth,
                                        const float* __restrict__ vtl,
                                        int hb, int s0, int tid)
{
    const float* ph = vth + (size_t)hb * HDIM * KPAD + s0;
    const float* pl = vtl + (size_t)hb * HDIM * KPAD + s0;
#pragma unroll
    for (int i = 0; i < 4; i++) {
        int u = tid + i * 256;
        int row = u >> 4, c = u & 15;
        uint32_t swc = (c & 8) | ((c ^ (row & 7)) & 7);
        uint32_t off = row * 256 + (swc << 4);
        cp_async16(dst + off, ph + (size_t)row * KPAD + c * 4);
        cp_async16(dst + 16384u + off, pl + (size_t)row * KPAD + c * 4);
    }
}

__global__ __launch_bounds__(256) void attn_cp(
    const float* __restrict__ qh, const float* __restrict__ ql,
    const float* __restrict__ kh, const float* __restrict__ kl,
    const float* __restrict__ vth, const float* __restrict__ vtl,
    float* __restrict__ att)
{
    extern __shared__ char smb[];
    const uint32_t sb = s2u(smb);
    float* sc  = (float*)(smb + SC_OFF);
    float* red = (float*)(smb + RED_OFF);

    const int tid = threadIdx.x, lane = tid & 31, wid = tid >> 5;
    const int wm = wid >> 1, wn = wid & 1;
    const int g = lane >> 3, l7 = lane & 7;
    const int q0 = blockIdx.x * 64;
    const int hb = blockIdx.y;
    const int gr = lane >> 2, gc = (lane & 3) << 1;

    // stage Q (once)
    {
        const float* ph = qh + ((size_t)(hb * SEQ + q0)) * HDIM;
        const float* pl = ql + ((size_t)(hb * SEQ + q0)) * HDIM;
#pragma unroll
        for (int i = 0; i < 4; i++) {
            int u = tid + i * 256;
            int row = u >> 4, c = u & 15;
            uint32_t swc = (c & 8) | ((c ^ (row & 7)) & 7);
            uint32_t off = row * 256 + (swc << 4);
            cp_async16(sb + off, ph + (size_t)row * HDIM + c * 4);
            cp_async16(sb + 16384u + off, pl + (size_t)row * HDIM + c * 4);
        }
        cp_commit();
    }
    // prime KV ring: K0 -> stage0, K1 -> stage1  (key window starts at storage idx q0)
    stage_k(sb + 32768u, kh, kl, hb, q0, tid);          cp_commit();
    stage_k(sb + 65536u, kh, kl, hb, q0 + 64, tid);     cp_commit();

    // ---- phase 1: scores ----
    for (int t = 0; t < 5; t++) {
        cp_wait1();
        __syncthreads();
        uint32_t skv = sb + 32768u + (uint32_t)(t & 1) * 32768u;

        float cfr[4][4];
#pragma unroll
        for (int nt = 0; nt < 4; nt++)
#pragma unroll
            for (int e = 0; e < 4; e++) cfr[nt][e] = 0.0f;

#pragma unroll
        for (int kt = 0; kt < 8; kt++) {
            uint32_t ah[4], al[4];
            {
                int row = wm * 16 + ((g & 1) << 3) + l7;
                int c = 2 * kt + (g >> 1);
                uint32_t swc = (c & 8) | ((c ^ (row & 7)) & 7);
                ldsm_x4(ah, sb + row * 256 + (swc << 4));
                ldsm_x4(al, sb + 16384u + row * 256 + (swc << 4));
            }
            uint32_t bh[4][2], bl[4][2];
#pragma unroll
            for (int p = 0; p < 2; p++) {
                int row = wn * 32 + p * 16 + ((g >> 1) << 3) + l7;
                int c = 2 * kt + (g & 1);
                uint32_t swc = (c & 8) | ((c ^ (row & 7)) & 7);
                uint32_t r4[4];
                ldsm_x4(r4, skv + row * 256 + (swc << 4));
                bh[2 * p][0] = r4[0]; bh[2 * p][1] = r4[1];
                bh[2 * p + 1][0] = r4[2]; bh[2 * p + 1][1] = r4[3];
                ldsm_x4(r4, skv + 16384u + row * 256 + (swc << 4));
                bl[2 * p][0] = r4[0]; bl[2 * p][1] = r4[1];
                bl[2 * p + 1][0] = r4[2]; bl[2 * p + 1][1] = r4[3];
            }
#pragma unroll
            for (int nt = 0; nt < 4; nt++) {
                mma_tf32(cfr[nt], ah, bh[nt]);
                mma_tf32(cfr[nt], ah, bl[nt]);
                mma_tf32(cfr[nt], al, bh[nt]);
            }
        }
        __syncthreads();
        // issue tile t+2 into this stage
        if (t + 2 < 5) stage_k(skv, kh, kl, hb, q0 + (t + 2) * 64, tid);
        else           stage_v(skv, vth, vtl, hb, q0 + (t + 2 - 5) * 64, tid);
        cp_commit();

        // masked score write
#pragma unroll
        for (int nt = 0; nt < 4; nt++) {
#pragma unroll
            for (int half = 0; half < 2; half++) {
                int row = wm * 16 + gr + half * 8;
                int qi = q0 + row;
#pragma unroll
                for (int e = 0; e < 2; e++) {
                    int col = wn * 32 + nt * 8 + gc + e;
                    int kj = q0 - 128 + t * 64 + col;
                    int rel = qi - kj;
                    bool valid = (kj >= 0) && (kj < SEQ) && (rel <= 128) && (rel >= -128);
                    sc[row * 321 + t * 64 + col] = valid ? cfr[nt][half * 2 + e] * 0.125f
                                                         : -1e30f;
                }
            }
        }
    }
    __syncthreads();

    // ---- phase 2: exact softmax over 320 cols ----
    {
        const int part = tid >> 6;
        const int row  = tid & 63;
        const int c0 = part * 80;
        float mx = -1e30f;
        for (int c = c0; c < c0 + 80; c++) mx = fmaxf(mx, sc[row * 321 + c]);
        red[part * 64 + row] = mx;
        __syncthreads();
        float m = fmaxf(fmaxf(red[row], red[64 + row]),
                        fmaxf(red[128 + row], red[192 + row]));
        __syncthreads();
        float sumv = 0.0f;
        for (int c = c0; c < c0 + 80; c++) {
            float e = __expf(sc[row * 321 + c] - m);
            sc[row * 321 + c] = e;
            sumv += e;
        }
        red[part * 64 + row] = sumv;
    }

    // ---- phase 3: PV ----
    float o[4][4];
#pragma unroll
    for (int nt = 0; nt < 4; nt++)
#pragma unroll
        for (int e = 0; e < 4; e++) o[nt][e] = 0.0f;

    for (int t = 0; t < 5; t++) {
        cp_wait1();
        __syncthreads();
        uint32_t skv = sb + 32768u + (uint32_t)((t + 1) & 1) * 32768u;  // tile u=5+t

#pragma unroll
        for (int kt = 0; kt < 8; kt++) {
            int kk = t * 64 + kt * 8 + (lane & 3);
            int r0 = wm * 16 + gr;
            float p00 = sc[r0 * 321 + kk];
            float p10 = sc[(r0 + 8) * 321 + kk];
            float p01 = sc[r0 * 321 + kk + 4];
            float p11 = sc[(r0 + 8) * 321 + kk + 4];
            float ah[4], al[4];
            ah[0] = tf32r(p00); al[0] = tf32r(p00 - ah[0]);
            ah[1] = tf32r(p10); al[1] = tf32r(p10 - ah[1]);
            ah[2] = tf32r(p01); al[2] = tf32r(p01 - ah[2]);
            ah[3] = tf32r(p11); al[3] = tf32r(p11 - ah[3]);

            uint32_t bh[4][2], bl[4][2];
#pragma unroll
            for (int p = 0; p < 2; p++) {
                int row = wn * 32 + p * 16 + ((g >> 1) << 3) + l7;
                int c = 2 * kt + (g & 1);
                uint32_t swc = (c & 8) | ((c ^ (row & 7)) & 7);
                uint32_t r4[4];
                ldsm_x4(r4, skv + row * 256 + (swc << 4));
                bh[2 * p][0] = r4[0]; bh[2 * p][1] = r4[1];
                bh[2 * p + 1][0] = r4[2]; bh[2 * p + 1][1] = r4[3];
                ldsm_x4(r4, skv + 16384u + row * 256 + (swc << 4));
                bl[2 * p][0] = r4[0]; bl[2 * p][1] = r4[1];
                bl[2 * p + 1][0] = r4[2]; bl[2 * p + 1][1] = r4[3];
            }
#pragma unroll
            for (int nt = 0; nt < 4; nt++) {
                mma_tf32(o[nt], (const uint32_t*)ah, bh[nt]);
                mma_tf32(o[nt], (const uint32_t*)ah, bl[nt]);
                mma_tf32(o[nt], (const uint32_t*)al, bh[nt]);
            }
        }
        __syncthreads();
        if (t + 2 < 5)
            stage_v(skv, vth, vtl, hb, q0 + (t + 2) * 64, tid);
        cp_commit();
    }

    // ---- epilogue: divide by row sums, store TF32-ROUNDED to att [B,S,H,D] ----
    const int b = hb >> 4, h = hb & 15;
#pragma unroll
    for (int half = 0; half < 2; half++) {
        int row = wm * 16 + gr + half * 8;
        float rs = red[row] + red[64 + row] + red[128 + row] + red[192 + row];
        float inv = 1.0f / rs;
        int qi = q0 + row;
        float* obase = att + ((size_t)((b * SEQ + qi) * HEADS + h)) * HDIM;
#pragma unroll
        for (int nt = 0; nt < 4; nt++) {
            int col = wn * 32 + nt * 8 + gc;
            float2 v;
            v.x = tf32r(o[nt][half * 2 + 0] * inv);
            v.y = tf32r(o[nt][half * 2 + 1] * inv);
            *(float2*)(obase + col) = v;
        }
    }
}

// ---------------------------------------------------------------------------
// Launch
// ---------------------------------------------------------------------------
extern "C" void kernel_launch(void* const* d_in, const int* in_sizes, int n_in,
                              void* d_out, int out_size)
{
    const float* hs   = (const float*)d_in[0];
    const float* wqkv = (const float*)d_in[1];
    const float* bqkv = (const float*)d_in[2];
    const float* wo   = (const float*)d_in[3];
    const float* bo   = (const float*)d_in[4];
    const float* rope = (const float*)d_in[5];
    float* out = (float*)d_out;

    float *qkv, *att, *hsr, *wqT, *woT, *qh, *ql, *kh, *kl, *vth, *vtl;
    cudaGetSymbolAddress((void**)&qkv, g_qkv);
    cudaGetSymbolAddress((void**)&att, g_att);
    cudaGetSymbolAddress((void**)&hsr, g_hsr);
    cudaGetSymbolAddress((void**)&wqT, g_wqT);
    cudaGetSymbolAddress((void**)&woT, g_woT);
    cudaGetSymbolAddress((void**)&qh, g_qh);
    cudaGetSymbolAddress((void**)&ql, g_ql);
    cudaGetSymbolAddress((void**)&kh, g_kh);
    cudaGetSymbolAddress((void**)&kl, g_kl);
    cudaGetSymbolAddress((void**)&vth, g_vth);
    cudaGetSymbolAddress((void**)&vtl, g_vtl);

    cudaFuncSetAttribute(gemm_tf32_cp,
                         cudaFuncAttributeMaxDynamicSharedMemorySize, GSMEM);
    cudaFuncSetAttribute(attn_cp,
                         cudaFuncAttributeMaxDynamicSharedMemorySize, ATT_SMEM);

    // 0) Pre-pass: tf32-round hs; transpose+round weights; zero attn pads
    round_tf32<<<(MROWS * KDIM) / 1024, 256>>>(hs, hsr, MROWS * KDIM);
    transpose_round<<<dim3(QKVW / 32, KDIM / 32), dim3(32, 8)>>>(wqkv, wqT, KDIM, QKVW);
    transpose_round<<<dim3(HID / 32, KDIM / 32), dim3(32, 8)>>>(wo, woT, KDIM, HID);
    pad_zero<<<4096, 256>>>(kh, kl, vth, vtl);

    // 1) QKV projection
    gemm_tf32_cp<<<dim3(QKVW / 128, MROWS / 128), 256, GSMEM>>>(hsr, wqT, bqkv, qkv, QKVW);

    // 2) RoPE + hi/lo split of q,k; V transpose + split
    rope_split<<<(1 << 21) / 256, 256>>>(qkv, rope, qh, ql, kh, kl);
    vt_split<<<dim3(SEQ / 32, HDIM / 32, NHB), dim3(32, 8)>>>(qkv, vth, vtl);

    // 3) Banded attention (cp.async + ldmatrix + 3xTF32 mma)
    attn_cp<<<dim3(SEQ / 64, NHB), 256, ATT_SMEM>>>(qh, ql, kh, kl, vth, vtl, att);

    // 4) Output projection
    gemm_tf32_cp<<<dim3(HID / 128, MROWS / 128), 256, GSMEM>>>(att, woT, bo, out, HID);
}

// round 12
// speedup vs baseline: 1.3625x; 1.3625x over previous
#include <cuda_runtime.h>
#include <cuda_bf16.h>
#include <cstdint>

// Problem constants
#define BATCH 2
#define SEQ   2048
#define HID   1024
#define HEADS 16
#define HDIM  64
#define QKVW  (3*HID)      // 3072
#define MROWS (BATCH*SEQ)  // 4096
#define KDIM  1024

// Scratch (device globals — no allocation allowed)
__device__ float g_qkv[(size_t)MROWS * QKVW];   // [B,S,3,H,D] (post-rope q,k)
__device__ float g_att[(size_t)MROWS * HID];    // [B,S,H,D] (tf32-rounded)
__device__ float g_hsr[(size_t)MROWS * KDIM];   // hs, tf32-rounded
__device__ float g_wqT[(size_t)QKVW * KDIM];    // Wqkv^T [N][K]
__device__ float g_woT[(size_t)HID * KDIM];     // Wo^T   [N][K]

// ---------------------------------------------------------------------------
// PTX helpers
// ---------------------------------------------------------------------------
__device__ __forceinline__ float tf32r(float x) {
    uint32_t u;
    asm("cvt.rna.tf32.f32 %0, %1;" : "=r"(u) : "f"(x));
    return __uint_as_float(u);
}
__device__ __forceinline__ uint32_t s2u(const void* p) {
    uint32_t a;
    asm("{ .reg .u64 t; cvta.to.shared.u64 t, %1; cvt.u32.u64 %0, t; }"
        : "=r"(a) : "l"(p));
    return a;
}
__device__ __forceinline__ void mma_tf32(float* d, const uint32_t* a, const uint32_t* b) {
    asm volatile(
        "mma.sync.aligned.m16n8k8.row.col.f32.tf32.tf32.f32 "
        "{%0,%1,%2,%3}, {%4,%5,%6,%7}, {%8,%9}, {%0,%1,%2,%3};\n"
        : "+f"(d[0]), "+f"(d[1]), "+f"(d[2]), "+f"(d[3])
        : "r"(a[0]), "r"(a[1]), "r"(a[2]), "r"(a[3]),
          "r"(b[0]), "r"(b[1]));
}
__device__ __forceinline__ void cp_async16(uint32_t saddr, const void* g) {
    asm volatile("cp.async.cg.shared.global [%0], [%1], 16;" :: "r"(saddr), "l"(g));
}
__device__ __forceinline__ void cp_commit() {
    asm volatile("cp.async.commit_group;" ::: "memory");
}
__device__ __forceinline__ void cp_wait1() {
    asm volatile("cp.async.wait_group 1;" ::: "memory");
}
__device__ __forceinline__ void ldsm_x4(uint32_t* r, uint32_t addr) {
    asm volatile("ldmatrix.sync.aligned.m8n8.x4.shared.b16 {%0,%1,%2,%3}, [%4];"
                 : "=r"(r[0]), "=r"(r[1]), "=r"(r[2]), "=r"(r[3]) : "r"(addr));
}

// ---------------------------------------------------------------------------
// Pre-pass kernels: tf32 rounding / transpose+round
// ---------------------------------------------------------------------------
__global__ void round_tf32(const float* __restrict__ x, float* __restrict__ y, int n)
{
    int i = (blockIdx.x * blockDim.x + threadIdx.x) * 4;
    if (i >= n) return;
    float4 v = *(const float4*)(x + i);
    v.x = tf32r(v.x); v.y = tf32r(v.y); v.z = tf32r(v.z); v.w = tf32r(v.w);
    *(float4*)(y + i) = v;
}

__global__ void transpose_round(const float* __restrict__ W, float* __restrict__ T,
                                int K, int N)
{
    __shared__ float t[32][33];
    int n0 = blockIdx.x * 32, k0 = blockIdx.y * 32;
    int tx = threadIdx.x, ty = threadIdx.y;
#pragma unroll
    for (int i = 0; i < 4; i++)
        t[ty + 8 * i][tx] = W[(size_t)(k0 + ty + 8 * i) * N + n0 + tx];
    __syncthreads();
#pragma unroll
    for (int i = 0; i < 4; i++)
        T[(size_t)(n0 + ty + 8 * i) * K + k0 + tx] = tf32r(t[tx][ty + 8 * i]);
}

// ---------------------------------------------------------------------------
// tf32 GEMM, cp.async + ldmatrix + mma, kt-fragment double buffering.
//   C[M,N] = A[M,1024] @ Bt[N,1024]^T + bias[N]   (+ optional fused RoPE)
// rope != nullptr: apply RoPE rotation to columns < 2048 (q,k regions).
// ---------------------------------------------------------------------------
#define GSMEM (3 * 32768)

__global__ __launch_bounds__(256, 2) void gemm_tf32_cp(
    const float* __restrict__ A, const float* __restrict__ Bt,
    const float* __restrict__ bias, float* __restrict__ C, int N,
    const float* __restrict__ rope)
{
    extern __shared__ char smc[];
    const uint32_t sbase = s2u(smc);
    const int tid = threadIdx.x, lane = tid & 31, wid = tid >> 5;
    const int wm = wid >> 1, wn = wid & 1;
    const int m0 = blockIdx.y * 128, n0 = blockIdx.x * 128;

    float acc[2][8][4];
#pragma unroll
    for (int i = 0; i < 2; i++)
#pragma unroll
        for (int j = 0; j < 8; j++)
#pragma unroll
            for (int c = 0; c < 4; c++) acc[i][j][c] = 0.0f;

#define ISSUE(ck, st)                                                         \
    {                                                                         \
        const float* pA_ = A + (size_t)m0 * KDIM + (ck) * 32;                 \
        const float* pB_ = Bt + (size_t)n0 * KDIM + (ck) * 32;                \
        uint32_t sa_ = sbase + (uint32_t)(st) * 32768u;                       \
        _Pragma("unroll")                                                     \
        for (int i_ = 0; i_ < 4; i_++) {                                      \
            int u_ = tid + i_ * 256;                                          \
            int row_ = u_ >> 3, c_ = u_ & 7;                                  \
            uint32_t off_ = row_ * 128 + ((c_ ^ (row_ & 7)) << 4);            \
            cp_async16(sa_ + off_, pA_ + (size_t)row_ * KDIM + c_ * 4);       \
            cp_async16(sa_ + 16384u + off_, pB_ + (size_t)row_ * KDIM + c_ * 4); \
        }                                                                     \
    }

#define LOADFRAG(kt, AF, BF)                                                  \
    {                                                                         \
        _Pragma("unroll")                                                     \
        for (int mt_ = 0; mt_ < 2; mt_++) {                                   \
            int row_ = wm * 32 + mt_ * 16 + ((g & 1) << 3) + l7;              \
            int c_ = 2 * (kt) + (g >> 1);                                     \
            ldsm_x4((AF)[mt_], sa + row_ * 128 + ((c_ ^ l7) << 4));           \
        }                                                                     \
        _Pragma("unroll")                                                     \
        for (int p_ = 0; p_ < 4; p_++) {                                      \
            int row_ = wn * 64 + p_ * 16 + ((g >> 1) << 3) + l7;              \
            int c_ = 2 * (kt) + (g & 1);                                      \
            uint32_t r4_[4];                                                  \
            ldsm_x4(r4_, sb2 + row_ * 128 + ((c_ ^ l7) << 4));                \
            (BF)[2 * p_][0] = r4_[0]; (BF)[2 * p_][1] = r4_[1];               \
            (BF)[2 * p_ + 1][0] = r4_[2]; (BF)[2 * p_ + 1][1] = r4_[3];       \
        }                                                                     \
    }

    ISSUE(0, 0); cp_commit();
    ISSUE(1, 1); cp_commit();

    const int g = lane >> 3, l7 = lane & 7;
    int st = 0;
    for (int ck = 0; ck < KDIM / 32; ck++) {
        cp_wait1();
        __syncthreads();
        int nst = st + 2; if (nst >= 3) nst -= 3;
        if (ck + 2 < KDIM / 32) ISSUE(ck + 2, nst);
        cp_commit();

        uint32_t sa = sbase + (uint32_t)st * 32768u;
        uint32_t sb2 = sa + 16384u;

        uint32_t af[2][2][4];
        uint32_t bf[2][8][2];
        LOADFRAG(0, af[0], bf[0]);
#pragma unroll
        for (int kt = 0; kt < 4; kt++) {
            if (kt < 3) LOADFRAG(kt + 1, af[(kt + 1) & 1], bf[(kt + 1) & 1]);
            const int cb = kt & 1;
#pragma unroll
            for (int mt = 0; mt < 2; mt++)
#pragma unroll
                for (int nt = 0; nt < 8; nt++)
                    mma_tf32(acc[mt][nt], af[cb][mt], bf[cb][nt]);
        }
        st++; if (st == 3) st = 0;
    }
#undef ISSUE
#undef LOADFRAG

    // ---- epilogue: bias (+ fused RoPE on q,k columns) + store ----
    const int gr = lane >> 2;
    const int gc = (lane & 3) << 1;
#pragma unroll
    for (int nt = 0; nt < 8; nt++) {
        int col = n0 + wn * 64 + nt * 8 + gc;
        float2 bb = *(const float2*)(bias + col);
        const bool do_rope = (rope != nullptr) && (col < 2 * HID);
        const int d2 = (col & 63) >> 1;
#pragma unroll
        for (int mt = 0; mt < 2; mt++) {
            int row = m0 + wm * 32 + mt * 16 + gr;
            float2 v0, v1;
            v0.x = acc[mt][nt][0] + bb.x;
            v0.y = acc[mt][nt][1] + bb.y;
            v1.x = acc[mt][nt][2] + bb.x;
            v1.y = acc[mt][nt][3] + bb.y;
            if (do_rope) {
                int p0 = row & 255;
                int p1 = (row + 8) & 255;
                float2 cs0 = *(const float2*)(rope + (p0 * 32 + d2) * 2);
                float2 cs1 = *(const float2*)(rope + (p1 * 32 + d2) * 2);
                float t0 = v0.x * cs0.x - v0.y * cs0.y;
                v0.y = v0.y * cs0.x + v0.x * cs0.y;
                v0.x = t0;
                float t1 = v1.x * cs1.x - v1.y * cs1.y;
                v1.y = v1.y * cs1.x + v1.x * cs1.y;
                v1.x = t1;
            }
            *(float2*)(C + (size_t)row * N + col)       = v0;
            *(float2*)(C + (size_t)(row + 8) * N + col) = v1;
        }
    }
}

// ---------------------------------------------------------------------------
// Banded attention with 3xTF32 mma (round-10 version, unchanged).
// ---------------------------------------------------------------------------
#define QT   64
#define SCW  321
#define ATTN_SMEM ((4*4096 + 64*SCW + 256) * (int)sizeof(float))

__global__ __launch_bounds__(256) void attn_mma(
    const float* __restrict__ qkv, float* __restrict__ att)
{
    extern __shared__ float smf[];
    float* Qh = smf;
    float* Ql = smf + 4096;
    float* Kh = smf + 8192;
    float* Kl = smf + 12288;
    float* sc = smf + 16384;
    float* red = sc + 64 * SCW;

    const int tid  = threadIdx.x;
    const int lane = tid & 31, wid = tid >> 5;
    const int wm = wid >> 1, wn = wid & 1;
    const int q0 = blockIdx.x * QT;
    const int h  = blockIdx.y, b = blockIdx.z;
    const int kb = q0 - 128;
    const int gr = lane >> 2, gc = (lane & 3) << 1;

    {
        const float* qbase = qkv + ((size_t)(b * SEQ + q0)) * QKVW + h * HDIM;
#pragma unroll
        for (int i = 0; i < 4; i++) {
            int idx = tid + i * 256;
            int row = idx >> 4, c4 = (idx & 15) << 2;
            float4 v = *(const float4*)(qbase + (size_t)row * QKVW + c4);
            float vv[4] = {v.x, v.y, v.z, v.w};
#pragma unroll
            for (int j = 0; j < 4; j++) {
                int k = c4 + j;
                int tm = row >> 4, tk = k >> 3, r = row & 15;
                int ln = ((r & 7) << 2) | (k & 3);
                int rg = (((k >> 2) & 1) << 1) | (r >> 3);
                int slot = ((tm * 8 + tk) << 7) + ((ln ^ tk) << 2) + rg;
                float hi = tf32r(vv[j]);
                Qh[slot] = hi;
                Ql[slot] = tf32r(vv[j] - hi);
            }
        }
    }

    for (int t = 0; t < 5; t++) {
        __syncthreads();
#pragma unroll
        for (int i = 0; i < 4; i++) {
            int idx = tid + i * 256;
            int key = idx >> 4, c4 = (idx & 15) << 2;
            int kj = kb + t * 64 + key;
            float4 v = make_float4(0.f, 0.f, 0.f, 0.f);
            if (kj >= 0 && kj < SEQ)
                v = *(const float4*)(qkv + ((size_t)(b * SEQ + kj)) * QKVW + HID + h * HDIM + c4);
            float vv[4] = {v.x, v.y, v.z, v.w};
#pragma unroll
            for (int j = 0; j < 4; j++) {
                int d = c4 + j;
                int kt = d >> 3, tn = key >> 3;
                int ln = ((key & 7) << 2) | (d & 3);
                int rg = (d >> 2) & 1;
                int slot = ((kt * 8 + tn) << 6) + ((ln ^ (tn & 7)) << 1) + rg;
                float hi = tf32r(vv[j]);
                Kh[slot] = hi;
                Kl[slot] = tf32r(vv[j] - hi);
            }
        }
        __syncthreads();

        float c[4][4];
#pragma unroll
        for (int nt = 0; nt < 4; nt++)
#pragma unroll
            for (int e = 0; e < 4; e++) c[nt][e] = 0.0f;

#pragma unroll
        for (int kt = 0; kt < 8; kt++) {
            uint4 ah = ((const uint4*)Qh)[((wm * 8 + kt) << 5) + (lane ^ kt)];
            uint4 al = ((const uint4*)Ql)[((wm * 8 + kt) << 5) + (lane ^ kt)];
#pragma unroll
            for (int nt = 0; nt < 4; nt++) {
                int tn = wn * 4 + nt;
                uint2 bh = ((const uint2*)Kh)[((kt * 8 + tn) << 5) + (lane ^ (tn & 7))];
                uint2 bl = ((const uint2*)Kl)[((kt * 8 + tn) << 5) + (lane ^ (tn & 7))];
                mma_tf32(c[nt], (const uint32_t*)&ah, (const uint32_t*)&bh);
                mma_tf32(c[nt], (const uint32_t*)&ah, (const uint32_t*)&bl);
                mma_tf32(c[nt], (const uint32_t*)&al, (const uint32_t*)&bh);
            }
        }
#pragma unroll
        for (int nt = 0; nt < 4; nt++) {
#pragma unroll
            for (int half = 0; half < 2; half++) {
                int row = wm * 16 + gr + half * 8;
                int qi = q0 + row;
#pragma unroll
                for (int e = 0; e < 2; e++) {
                    int col = wn * 32 + nt * 8 + gc + e;
                    int kj = kb + t * 64 + col;
                    int rel = qi - kj;
                    bool valid = (kj >= 0) && (kj < SEQ) && (rel <= 128) && (rel >= -128);
                    sc[row * SCW + t * 64 + col] = valid ? c[nt][half * 2 + e] * 0.125f : -1e30f;
                }
            }
        }
    }
    __syncthreads();

    {
        const int part = tid >> 6;
        const int row  = tid & 63;
        const int c0 = part * 80;
        float mx = -1e30f;
        for (int c = c0; c < c0 + 80; c++) mx = fmaxf(mx, sc[row * SCW + c]);
        red[part * 64 + row] = mx;
        __syncthreads();
        float m = fmaxf(fmaxf(red[row], red[64 + row]),
                        fmaxf(red[128 + row], red[192 + row]));
        __syncthreads();
        float sumv = 0.0f;
        for (int c = c0; c < c0 + 80; c++) {
            float e = __expf(sc[row * SCW + c] - m);
            sc[row * SCW + c] = e;
            sumv += e;
        }
        red[part * 64 + row] = sumv;
    }

    float o[4][4];
#pragma unroll
    for (int nt = 0; nt < 4; nt++)
#pragma unroll
        for (int e = 0; e < 4; e++) o[nt][e] = 0.0f;

    for (int t = 0; t < 5; t++) {
        __syncthreads();
#pragma unroll
        for (int i = 0; i < 4; i++) {
            int idx = tid + i * 256;
            int key = idx >> 4, c4 = (idx & 15) << 2;
            int kj = kb + t * 64 + key;
            float4 v = make_float4(0.f, 0.f, 0.f, 0.f);
            if (kj >= 0 && kj < SEQ)
                v = *(const float4*)(qkv + ((size_t)(b * SEQ + kj)) * QKVW + 2 * HID + h * HDIM + c4);
            float vv[4] = {v.x, v.y, v.z, v.w};
#pragma unroll
            for (int j = 0; j < 4; j++) {
                int d = c4 + j;
                int kt = key >> 3, tn = d >> 3;
                int ln = ((d & 7) << 2) | (key & 3);
                int rg = (key >> 2) & 1;
                int slot = ((kt * 8 + tn) << 6) + ((ln ^ (tn & 7)) << 1) + rg;
                float hi = tf32r(vv[j]);
                Kh[slot] = hi;
                Kl[slot] = tf32r(vv[j] - hi);
            }
        }
        __syncthreads();

#pragma unroll
        for (int kt = 0; kt < 8; kt++) {
            int kk = t * 64 + kt * 8 + (lane & 3);
            int r0 = wm * 16 + gr;
            float p00 = sc[r0 * SCW + kk];
            float p10 = sc[(r0 + 8) * SCW + kk];
            float p01 = sc[r0 * SCW + kk + 4];
            float p11 = sc[(r0 + 8) * SCW + kk + 4];
            float ah[4], al[4];
            ah[0] = tf32r(p00); al[0] = tf32r(p00 - ah[0]);
            ah[1] = tf32r(p10); al[1] = tf32r(p10 - ah[1]);
            ah[2] = tf32r(p01); al[2] = tf32r(p01 - ah[2]);
            ah[3] = tf32r(p11); al[3] = tf32r(p11 - ah[3]);
#pragma unroll
            for (int nt = 0; nt < 4; nt++) {
                int tn = wn * 4 + nt;
                uint2 bh = ((const uint2*)Kh)[((kt * 8 + tn) << 5) + (lane ^ (tn & 7))];
                uint2 bl = ((const uint2*)Kl)[((kt * 8 + tn) << 5) + (lane ^ (tn & 7))];
                mma_tf32(o[nt], (const uint32_t*)ah, (const uint32_t*)&bh);
                mma_tf32(o[nt], (const uint32_t*)ah, (const uint32_t*)&bl);
                mma_tf32(o[nt], (const uint32_t*)al, (const uint32_t*)&bh);
            }
        }
    }

    // epilogue: divide by row sums, store TF32-ROUNDED to att [B,S,H,D]
#pragma unroll
    for (int half = 0; half < 2; half++) {
        int row = wm * 16 + gr + half * 8;
        float rs = red[row] + red[64 + row] + red[128 + row] + red[192 + row];
        float inv = 1.0f / rs;
        int qi = q0 + row;
        float* obase = att + ((size_t)((b * SEQ + qi) * HEADS + h)) * HDIM;
#pragma unroll
        for (int nt = 0; nt < 4; nt++) {
            int col = wn * 32 + nt * 8 + gc;
            float2 v;
            v.x = tf32r(o[nt][half * 2 + 0] * inv);
            v.y = tf32r(o[nt][half * 2 + 1] * inv);
            *(float2*)(obase + col) = v;
        }
    }
}

// ---------------------------------------------------------------------------
// Launch
// ---------------------------------------------------------------------------
extern "C" void kernel_launch(void* const* d_in, const int* in_sizes, int n_in,
                              void* d_out, int out_size)
{
    const float* hs   = (const float*)d_in[0];
    const float* wqkv = (const float*)d_in[1];
    const float* bqkv = (const float*)d_in[2];
    const float* wo   = (const float*)d_in[3];
    const float* bo   = (const float*)d_in[4];
    const float* rope = (const float*)d_in[5];
    float* out = (float*)d_out;

    float *qkv, *att, *hsr, *wqT, *woT;
    cudaGetSymbolAddress((void**)&qkv, g_qkv);
    cudaGetSymbolAddress((void**)&att, g_att);
    cudaGetSymbolAddress((void**)&hsr, g_hsr);
    cudaGetSymbolAddress((void**)&wqT, g_wqT);
    cudaGetSymbolAddress((void**)&woT, g_woT);

    cudaFuncSetAttribute(gemm_tf32_cp,
                         cudaFuncAttributeMaxDynamicSharedMemorySize, GSMEM);
    cudaFuncSetAttribute(attn_mma,
                         cudaFuncAttributeMaxDynamicSharedMemorySize, ATTN_SMEM);

    // 0) Pre-pass: tf32-round hs; transpose+round weights to [N][K]
    round_tf32<<<(MROWS * KDIM) / 1024, 256>>>(hs, hsr, MROWS * KDIM);
    transpose_round<<<dim3(QKVW / 32, KDIM / 32), dim3(32, 8)>>>(wqkv, wqT, KDIM, QKVW);
    transpose_round<<<dim3(HID / 32, KDIM / 32), dim3(32, 8)>>>(wo, woT, KDIM, HID);

    // 1) QKV projection with FUSED RoPE epilogue
    gemm_tf32_cp<<<dim3(QKVW / 128, MROWS / 128), 256, GSMEM>>>(
        hsr, wqT, bqkv, qkv, QKVW, rope);

    // 2) Banded attention (3xTF32 mma)
    attn_mma<<<dim3(SEQ / QT, HEADS, BATCH), 256, ATTN_SMEM>>>(qkv, att);

    // 3) Output projection (no rope)
    gemm_tf32_cp<<<dim3(HID / 128, MROWS / 128), 256, GSMEM>>>(
        att, woT, bo, out, HID, nullptr);
}